// round 2
// baseline (speedup 1.0000x reference)
#include <cuda_runtime.h>
#include <math.h>

#define NB   8192
#define NIN  1024
#define NHID 4096
#define NOUT 1024
#define NE   8
#define EPS  1e-5f

// Scratch (allocation-free rule: __device__ globals)
__device__ float g_H[(size_t)NE * NB * NHID];  // 1.07 GB: expert-major [E][B][HID]
__device__ float g_Y[(size_t)NE * NB * NOUT];  // 268 MB:  [E][B][OUT]

// ---------------------------------------------------------------------------
// Helpers
// ---------------------------------------------------------------------------
__device__ __forceinline__ float gelu_exact(float v) {
    return 0.5f * v * (1.0f + erff(v * 0.70710678118654752f));
}

// Block-wide sum of (s, s2). Requires blockDim.x == 256. Leaves results in s/s2
// for every thread. Safe to call repeatedly in a loop.
__device__ __forceinline__ void block_sum2(float& s, float& s2) {
    __shared__ float sh[2][8];
    #pragma unroll
    for (int o = 16; o > 0; o >>= 1) {
        s  += __shfl_xor_sync(0xffffffffu, s,  o);
        s2 += __shfl_xor_sync(0xffffffffu, s2, o);
    }
    const int w    = threadIdx.x >> 5;
    const int lane = threadIdx.x & 31;
    if (lane == 0) { sh[0][w] = s; sh[1][w] = s2; }
    __syncthreads();
    float t = 0.f, t2 = 0.f;
    #pragma unroll
    for (int i = 0; i < 8; i++) { t += sh[0][i]; t2 += sh[1][i]; }
    s = t; s2 = t2;
    __syncthreads();   // protect sh against reuse in caller loops
}

// ---------------------------------------------------------------------------
// Batched GEMM + bias: C[e] = A([e]) @ B[e] + bias[e]
// A row-major [M,K] (optionally per-expert), B row-major [K,N], C [M,N].
// 128x128 block tile, 8x8 thread tile, BK=8, double-buffered smem.
// ---------------------------------------------------------------------------
template<bool A_EXP>
__global__ __launch_bounds__(256, 2)
void gemm_bias(const float* __restrict__ A, const float* __restrict__ Bm,
               const float* __restrict__ bias, float* __restrict__ C,
               int M, int N, int K)
{
    constexpr int BM = 128, BN = 128, BK = 8, TM = 8, TN = 8;
    const int e = blockIdx.z;
    const float* Ae = A + (A_EXP ? (size_t)e * M * K : (size_t)0);
    const float* Be = Bm + (size_t)e * K * N;
    const float* bz = bias + (size_t)e * N;
    float* Ce = C + (size_t)e * M * N;

    __shared__ float As[2][BK][BM];   // A transposed: As[k][m]
    __shared__ float Bs[2][BK][BN];

    const int tid  = threadIdx.x;
    const int trow = (tid >> 4) * TM;   // 0..120
    const int tcol = (tid & 15) * TN;   // 0..120
    const int row0 = blockIdx.y * BM;
    const int col0 = blockIdx.x * BN;

    // A tile load map: 128 rows x 8 cols, one float4 per thread
    const int a_row = tid >> 1;
    const int a_col = (tid & 1) * 4;
    // B tile load map: 8 rows x 128 cols, one float4 per thread (coalesced)
    const int b_row = tid >> 5;
    const int b_col = (tid & 31) * 4;

    float acc[TM][TN] = {};

    auto load_tile = [&](int dst, int k0) {
        float4 av = *reinterpret_cast<const float4*>(
            Ae + (size_t)(row0 + a_row) * K + k0 + a_col);
        As[dst][a_col + 0][a_row] = av.x;
        As[dst][a_col + 1][a_row] = av.y;
        As[dst][a_col + 2][a_row] = av.z;
        As[dst][a_col + 3][a_row] = av.w;
        float4 bv = *reinterpret_cast<const float4*>(
            Be + (size_t)(k0 + b_row) * N + col0 + b_col);
        *reinterpret_cast<float4*>(&Bs[dst][b_row][b_col]) = bv;
    };

    load_tile(0, 0);
    __syncthreads();

    int buf = 0;
    for (int k0 = 0; k0 < K; k0 += BK) {
        if (k0 + BK < K) load_tile(buf ^ 1, k0 + BK);
        #pragma unroll
        for (int kk = 0; kk < BK; kk++) {
            float ar[TM], br[TN];
            *reinterpret_cast<float4*>(&ar[0]) =
                *reinterpret_cast<const float4*>(&As[buf][kk][trow]);
            *reinterpret_cast<float4*>(&ar[4]) =
                *reinterpret_cast<const float4*>(&As[buf][kk][trow + 4]);
            *reinterpret_cast<float4*>(&br[0]) =
                *reinterpret_cast<const float4*>(&Bs[buf][kk][tcol]);
            *reinterpret_cast<float4*>(&br[4]) =
                *reinterpret_cast<const float4*>(&Bs[buf][kk][tcol + 4]);
            #pragma unroll
            for (int i = 0; i < TM; i++)
                #pragma unroll
                for (int j = 0; j < TN; j++)
                    acc[i][j] = fmaf(ar[i], br[j], acc[i][j]);
        }
        __syncthreads();
        buf ^= 1;
    }

    float bv[TN];
    #pragma unroll
    for (int j = 0; j < TN; j++) bv[j] = bz[col0 + tcol + j];

    #pragma unroll
    for (int i = 0; i < TM; i++) {
        float* cp = Ce + (size_t)(row0 + trow + i) * N + col0 + tcol;
        #pragma unroll
        for (int j = 0; j < TN; j += 4) {
            float4 o;
            o.x = acc[i][j + 0] + bv[j + 0];
            o.y = acc[i][j + 1] + bv[j + 1];
            o.z = acc[i][j + 2] + bv[j + 2];
            o.w = acc[i][j + 3] + bv[j + 3];
            *reinterpret_cast<float4*>(cp + j) = o;
        }
    }
}

// ---------------------------------------------------------------------------
// In-place LayerNorm + exact GELU over rows of length L. One block per row.
// Layout: X[row * L], row = e * NB + b. gamma/beta are [E, L].
// ---------------------------------------------------------------------------
template<int L>
__global__ __launch_bounds__(256)
void ln_gelu_inplace(float* __restrict__ X, const float* __restrict__ gamma,
                     const float* __restrict__ beta)
{
    constexpr int V = L / 1024;   // float4s per thread at 256 threads
    const size_t row = blockIdx.x;
    const int e = (int)(row / NB);
    float4* xr = reinterpret_cast<float4*>(X + row * (size_t)L);
    const float4* gp = reinterpret_cast<const float4*>(gamma + (size_t)e * L);
    const float4* bp = reinterpret_cast<const float4*>(beta  + (size_t)e * L);

    float4 v[V];
    float s = 0.f, s2 = 0.f;
    #pragma unroll
    for (int i = 0; i < V; i++) {
        v[i] = xr[i * 256 + threadIdx.x];
        s  += v[i].x + v[i].y + v[i].z + v[i].w;
        s2 += v[i].x * v[i].x + v[i].y * v[i].y + v[i].z * v[i].z + v[i].w * v[i].w;
    }
    block_sum2(s, s2);
    const float mean = s * (1.0f / L);
    const float var  = s2 * (1.0f / L) - mean * mean;
    const float rstd = rsqrtf(var + EPS);

    #pragma unroll
    for (int i = 0; i < V; i++) {
        float4 g4 = gp[i * 256 + threadIdx.x];
        float4 b4 = bp[i * 256 + threadIdx.x];
        float4 o;
        o.x = gelu_exact((v[i].x - mean) * rstd * g4.x + b4.x);
        o.y = gelu_exact((v[i].y - mean) * rstd * g4.y + b4.y);
        o.z = gelu_exact((v[i].z - mean) * rstd * g4.z + b4.z);
        o.w = gelu_exact((v[i].w - mean) * rstd * g4.w + b4.w);
        xr[i * 256 + threadIdx.x] = o;
    }
}

// ---------------------------------------------------------------------------
// Final: per (b,e) row LN + GELU over OUT, then out[b,:] = sum_e w[b,e]*act.
// One block per token b. Reads g_Y directly.
// ---------------------------------------------------------------------------
__global__ __launch_bounds__(256)
void combine_kernel(const float* __restrict__ w,
                    const float* __restrict__ g2, const float* __restrict__ be2,
                    float* __restrict__ out)
{
    const int b   = blockIdx.x;
    const int tid = threadIdx.x;
    float acc[4] = {0.f, 0.f, 0.f, 0.f};   // NOUT / 256

    for (int e = 0; e < NE; e++) {
        const float* yr = g_Y + ((size_t)e * NB + b) * NOUT;
        float vv[4];
        float s = 0.f, s2 = 0.f;
        #pragma unroll
        for (int i = 0; i < 4; i++) {
            vv[i] = yr[tid + i * 256];
            s += vv[i]; s2 += vv[i] * vv[i];
        }
        block_sum2(s, s2);
        const float mean = s * (1.0f / NOUT);
        const float rstd = rsqrtf(s2 * (1.0f / NOUT) - mean * mean + EPS);
        const float we   = w[(size_t)b * NE + e];
        #pragma unroll
        for (int i = 0; i < 4; i++) {
            const int o = tid + i * 256;
            const float val = (vv[i] - mean) * rstd * g2[(size_t)e * NOUT + o]
                              + be2[(size_t)e * NOUT + o];
            acc[i] += we * gelu_exact(val);
        }
    }
    #pragma unroll
    for (int i = 0; i < 4; i++)
        out[(size_t)b * NOUT + tid + i * 256] = acc[i];
}

// ---------------------------------------------------------------------------
extern "C" void kernel_launch(void* const* d_in, const int* in_sizes, int n_in,
                              void* d_out, int out_size)
{
    const float* x   = (const float*)d_in[0];
    const float* wts = (const float*)d_in[1];
    const float* W1  = (const float*)d_in[2];
    const float* b1  = (const float*)d_in[3];
    const float* g1  = (const float*)d_in[4];
    const float* be1 = (const float*)d_in[5];
    const float* W2  = (const float*)d_in[6];
    const float* b2  = (const float*)d_in[7];
    const float* g2  = (const float*)d_in[8];
    const float* be2 = (const float*)d_in[9];
    float* out = (float*)d_out;

    static float* H_ptr = nullptr;
    static float* Y_ptr = nullptr;
    if (!H_ptr) {
        cudaGetSymbolAddress((void**)&H_ptr, g_H);
        cudaGetSymbolAddress((void**)&Y_ptr, g_Y);
    }

    dim3 blk(256);

    // 1) H[e] = x @ W1[e] + b1[e]          [B, HID] per expert
    gemm_bias<false><<<dim3(NHID / 128, NB / 128, NE), blk>>>(
        x, W1, b1, H_ptr, NB, NHID, NIN);

    // 2) H = gelu(layernorm(H))            in place
    ln_gelu_inplace<NHID><<<NE * NB, blk>>>(H_ptr, g1, be1);

    // 3) Y[e] = H[e] @ W2[e] + b2[e]       [B, OUT] per expert
    gemm_bias<true><<<dim3(NOUT / 128, NB / 128, NE), blk>>>(
        H_ptr, W2, b2, Y_ptr, NB, NOUT, NHID);

    // 4) out[b] = sum_e w[b,e] * gelu(layernorm(Y[e,b]))
    combine_kernel<<<NB, blk>>>(wts, g2, be2, out);
}

// round 3
// speedup vs baseline: 1.0001x; 1.0001x over previous
#include <cuda_runtime.h>
#include <math.h>

#define NB   8192
#define NIN  1024
#define NHID 4096
#define NOUT 1024
#define NE   8
#define EPS  1e-5f

// Scratch (allocation-free rule: __device__ globals)
__device__ float g_H[(size_t)NE * NB * NHID];  // 1.07 GB: expert-major [E][B][HID]
__device__ float g_Y[(size_t)NE * NB * NOUT];  // 268 MB:  [E][B][OUT]

// ---------------------------------------------------------------------------
// Helpers
// ---------------------------------------------------------------------------
__device__ __forceinline__ float gelu_exact(float v) {
    return 0.5f * v * (1.0f + erff(v * 0.70710678118654752f));
}

// Block-wide sum of (s, s2). Requires blockDim.x == 256. Leaves results in s/s2
// for every thread. Safe to call repeatedly in a loop.
__device__ __forceinline__ void block_sum2(float& s, float& s2) {
    __shared__ float sh[2][8];
    #pragma unroll
    for (int o = 16; o > 0; o >>= 1) {
        s  += __shfl_xor_sync(0xffffffffu, s,  o);
        s2 += __shfl_xor_sync(0xffffffffu, s2, o);
    }
    const int w    = threadIdx.x >> 5;
    const int lane = threadIdx.x & 31;
    if (lane == 0) { sh[0][w] = s; sh[1][w] = s2; }
    __syncthreads();
    float t = 0.f, t2 = 0.f;
    #pragma unroll
    for (int i = 0; i < 8; i++) { t += sh[0][i]; t2 += sh[1][i]; }
    s = t; s2 = t2;
    __syncthreads();   // protect sh against reuse in caller loops
}

// ---------------------------------------------------------------------------
// Batched GEMM + bias: C[e] = A([e]) @ B[e] + bias[e]
// A row-major [M,K] (optionally per-expert), B row-major [K,N], C [M,N].
// 128x128 block tile, 8x8 thread tile, BK=8, double-buffered smem.
// ---------------------------------------------------------------------------
template<bool A_EXP>
__global__ __launch_bounds__(256, 2)
void gemm_bias(const float* __restrict__ A, const float* __restrict__ Bm,
               const float* __restrict__ bias, float* __restrict__ C,
               int M, int N, int K)
{
    constexpr int BM = 128, BN = 128, BK = 8, TM = 8, TN = 8;
    const int e = blockIdx.z;
    const float* Ae = A + (A_EXP ? (size_t)e * M * K : (size_t)0);
    const float* Be = Bm + (size_t)e * K * N;
    const float* bz = bias + (size_t)e * N;
    float* Ce = C + (size_t)e * M * N;

    __shared__ float As[2][BK][BM];   // A transposed: As[k][m]
    __shared__ float Bs[2][BK][BN];

    const int tid  = threadIdx.x;
    const int trow = (tid >> 4) * TM;   // 0..120
    const int tcol = (tid & 15) * TN;   // 0..120
    const int row0 = blockIdx.y * BM;
    const int col0 = blockIdx.x * BN;

    // A tile load map: 128 rows x 8 cols, one float4 per thread
    const int a_row = tid >> 1;
    const int a_col = (tid & 1) * 4;
    // B tile load map: 8 rows x 128 cols, one float4 per thread (coalesced)
    const int b_row = tid >> 5;
    const int b_col = (tid & 31) * 4;

    float acc[TM][TN] = {};

    auto load_tile = [&](int dst, int k0) {
        float4 av = *reinterpret_cast<const float4*>(
            Ae + (size_t)(row0 + a_row) * K + k0 + a_col);
        As[dst][a_col + 0][a_row] = av.x;
        As[dst][a_col + 1][a_row] = av.y;
        As[dst][a_col + 2][a_row] = av.z;
        As[dst][a_col + 3][a_row] = av.w;
        float4 bv = *reinterpret_cast<const float4*>(
            Be + (size_t)(k0 + b_row) * N + col0 + b_col);
        *reinterpret_cast<float4*>(&Bs[dst][b_row][b_col]) = bv;
    };

    load_tile(0, 0);
    __syncthreads();

    int buf = 0;
    for (int k0 = 0; k0 < K; k0 += BK) {
        if (k0 + BK < K) load_tile(buf ^ 1, k0 + BK);
        #pragma unroll
        for (int kk = 0; kk < BK; kk++) {
            float ar[TM], br[TN];
            *reinterpret_cast<float4*>(&ar[0]) =
                *reinterpret_cast<const float4*>(&As[buf][kk][trow]);
            *reinterpret_cast<float4*>(&ar[4]) =
                *reinterpret_cast<const float4*>(&As[buf][kk][trow + 4]);
            *reinterpret_cast<float4*>(&br[0]) =
                *reinterpret_cast<const float4*>(&Bs[buf][kk][tcol]);
            *reinterpret_cast<float4*>(&br[4]) =
                *reinterpret_cast<const float4*>(&Bs[buf][kk][tcol + 4]);
            #pragma unroll
            for (int i = 0; i < TM; i++)
                #pragma unroll
                for (int j = 0; j < TN; j++)
                    acc[i][j] = fmaf(ar[i], br[j], acc[i][j]);
        }
        __syncthreads();
        buf ^= 1;
    }

    float bv[TN];
    #pragma unroll
    for (int j = 0; j < TN; j++) bv[j] = bz[col0 + tcol + j];

    #pragma unroll
    for (int i = 0; i < TM; i++) {
        float* cp = Ce + (size_t)(row0 + trow + i) * N + col0 + tcol;
        #pragma unroll
        for (int j = 0; j < TN; j += 4) {
            float4 o;
            o.x = acc[i][j + 0] + bv[j + 0];
            o.y = acc[i][j + 1] + bv[j + 1];
            o.z = acc[i][j + 2] + bv[j + 2];
            o.w = acc[i][j + 3] + bv[j + 3];
            *reinterpret_cast<float4*>(cp + j) = o;
        }
    }
}

// ---------------------------------------------------------------------------
// In-place LayerNorm + exact GELU over rows of length L. One block per row.
// Layout: X[row * L], row = e * NB + b. gamma/beta are [E, L].
// ---------------------------------------------------------------------------
template<int L>
__global__ __launch_bounds__(256)
void ln_gelu_inplace(float* __restrict__ X, const float* __restrict__ gamma,
                     const float* __restrict__ beta)
{
    constexpr int V = L / 1024;   // float4s per thread at 256 threads
    const size_t row = blockIdx.x;
    const int e = (int)(row / NB);
    float4* xr = reinterpret_cast<float4*>(X + row * (size_t)L);
    const float4* gp = reinterpret_cast<const float4*>(gamma + (size_t)e * L);
    const float4* bp = reinterpret_cast<const float4*>(beta  + (size_t)e * L);

    float4 v[V];
    float s = 0.f, s2 = 0.f;
    #pragma unroll
    for (int i = 0; i < V; i++) {
        v[i] = xr[i * 256 + threadIdx.x];
        s  += v[i].x + v[i].y + v[i].z + v[i].w;
        s2 += v[i].x * v[i].x + v[i].y * v[i].y + v[i].z * v[i].z + v[i].w * v[i].w;
    }
    block_sum2(s, s2);
    const float mean = s * (1.0f / L);
    const float var  = s2 * (1.0f / L) - mean * mean;
    const float rstd = rsqrtf(var + EPS);

    #pragma unroll
    for (int i = 0; i < V; i++) {
        float4 g4 = gp[i * 256 + threadIdx.x];
        float4 b4 = bp[i * 256 + threadIdx.x];
        float4 o;
        o.x = gelu_exact((v[i].x - mean) * rstd * g4.x + b4.x);
        o.y = gelu_exact((v[i].y - mean) * rstd * g4.y + b4.y);
        o.z = gelu_exact((v[i].z - mean) * rstd * g4.z + b4.z);
        o.w = gelu_exact((v[i].w - mean) * rstd * g4.w + b4.w);
        xr[i * 256 + threadIdx.x] = o;
    }
}

// ---------------------------------------------------------------------------
// Final: per (b,e) row LN + GELU over OUT, then out[b,:] = sum_e w[b,e]*act.
// One block per token b. Reads g_Y directly.
// ---------------------------------------------------------------------------
__global__ __launch_bounds__(256)
void combine_kernel(const float* __restrict__ w,
                    const float* __restrict__ g2, const float* __restrict__ be2,
                    float* __restrict__ out)
{
    const int b   = blockIdx.x;
    const int tid = threadIdx.x;
    float acc[4] = {0.f, 0.f, 0.f, 0.f};   // NOUT / 256

    for (int e = 0; e < NE; e++) {
        const float* yr = g_Y + ((size_t)e * NB + b) * NOUT;
        float vv[4];
        float s = 0.f, s2 = 0.f;
        #pragma unroll
        for (int i = 0; i < 4; i++) {
            vv[i] = yr[tid + i * 256];
            s += vv[i]; s2 += vv[i] * vv[i];
        }
        block_sum2(s, s2);
        const float mean = s * (1.0f / NOUT);
        const float rstd = rsqrtf(s2 * (1.0f / NOUT) - mean * mean + EPS);
        const float we   = w[(size_t)b * NE + e];
        #pragma unroll
        for (int i = 0; i < 4; i++) {
            const int o = tid + i * 256;
            const float val = (vv[i] - mean) * rstd * g2[(size_t)e * NOUT + o]
                              + be2[(size_t)e * NOUT + o];
            acc[i] += we * gelu_exact(val);
        }
    }
    #pragma unroll
    for (int i = 0; i < 4; i++)
        out[(size_t)b * NOUT + tid + i * 256] = acc[i];
}

// ---------------------------------------------------------------------------
extern "C" void kernel_launch(void* const* d_in, const int* in_sizes, int n_in,
                              void* d_out, int out_size)
{
    const float* x   = (const float*)d_in[0];
    const float* wts = (const float*)d_in[1];
    const float* W1  = (const float*)d_in[2];
    const float* b1  = (const float*)d_in[3];
    const float* g1  = (const float*)d_in[4];
    const float* be1 = (const float*)d_in[5];
    const float* W2  = (const float*)d_in[6];
    const float* b2  = (const float*)d_in[7];
    const float* g2  = (const float*)d_in[8];
    const float* be2 = (const float*)d_in[9];
    float* out = (float*)d_out;

    static float* H_ptr = nullptr;
    static float* Y_ptr = nullptr;
    if (!H_ptr) {
        cudaGetSymbolAddress((void**)&H_ptr, g_H);
        cudaGetSymbolAddress((void**)&Y_ptr, g_Y);
    }

    dim3 blk(256);

    // 1) H[e] = x @ W1[e] + b1[e]          [B, HID] per expert
    gemm_bias<false><<<dim3(NHID / 128, NB / 128, NE), blk>>>(
        x, W1, b1, H_ptr, NB, NHID, NIN);

    // 2) H = gelu(layernorm(H))            in place
    ln_gelu_inplace<NHID><<<NE * NB, blk>>>(H_ptr, g1, be1);

    // 3) Y[e] = H[e] @ W2[e] + b2[e]       [B, OUT] per expert
    gemm_bias<true><<<dim3(NOUT / 128, NB / 128, NE), blk>>>(
        H_ptr, W2, b2, Y_ptr, NB, NOUT, NHID);

    // 4) out[b] = sum_e w[b,e] * gelu(layernorm(Y[e,b]))
    combine_kernel<<<NB, blk>>>(wts, g2, be2, out);
}

// round 5
// speedup vs baseline: 2.8522x; 2.8520x over previous
#include <cuda_runtime.h>
#include <cuda_bf16.h>
#include <math.h>
#include <stdint.h>

#define NB   8192
#define NIN  1024
#define NHID 4096
#define NOUT 1024
#define NE   8
#define EPS  1e-5f

// Packed operand layout: per 32 K-elems, 128B: [32 hi bf16][32 lo bf16]
__device__ __align__(256) __nv_bfloat16 g_Px [(size_t)NB * 2 * NIN];
__device__ __align__(256) __nv_bfloat16 g_Wp1[(size_t)NE * NHID * 2 * NIN];
__device__ __align__(256) __nv_bfloat16 g_Wp2[(size_t)NE * NOUT * 2 * NHID];
__device__ __align__(256) float         g_H  [(size_t)NE * NB * NHID];
__device__ __align__(256) __nv_bfloat16 g_Hp [(size_t)NE * NB * 2 * NHID];
__device__ __align__(256) float         g_Y  [(size_t)NE * NB * NOUT];

__device__ __forceinline__ uint32_t smem_u32(const void* p) {
    return (uint32_t)__cvta_generic_to_shared(p);
}
__device__ __forceinline__ float gelu_exact(float v) {
    return 0.5f * v * (1.0f + erff(v * 0.70710678118654752f));
}
__device__ __forceinline__ void block_sum2(float& s, float& s2) {
    __shared__ float sh[2][8];
    #pragma unroll
    for (int o = 16; o > 0; o >>= 1) {
        s  += __shfl_xor_sync(0xffffffffu, s,  o);
        s2 += __shfl_xor_sync(0xffffffffu, s2, o);
    }
    const int w = threadIdx.x >> 5, lane = threadIdx.x & 31;
    if (lane == 0) { sh[0][w] = s; sh[1][w] = s2; }
    __syncthreads();
    float t = 0.f, t2 = 0.f;
    #pragma unroll
    for (int i = 0; i < 8; i++) { t += sh[0][i]; t2 += sh[1][i]; }
    s = t; s2 = t2;
    __syncthreads();
}
__device__ __forceinline__ void split_bf16(float v, __nv_bfloat16& h, __nv_bfloat16& l) {
    h = __float2bfloat16(v);
    l = __float2bfloat16(v - __bfloat162float(h));
}
__device__ __forceinline__ uint32_t pack2(__nv_bfloat16 a, __nv_bfloat16 b) {
    return (uint32_t)__bfloat16_as_ushort(a) | ((uint32_t)__bfloat16_as_ushort(b) << 16);
}

// ---------------- prep kernels ----------------
__global__ __launch_bounds__(256)
void split_x_kernel(const float* __restrict__ X, __nv_bfloat16* __restrict__ P)
{
    const size_t row = blockIdx.x;
    const int tid = threadIdx.x;
    const float4 v = ((const float4*)(X + row * NIN))[tid];
    const int col = tid * 4, blk = col >> 5, w = col & 31;
    __nv_bfloat16 h0,h1,h2,h3,l0,l1,l2,l3;
    split_bf16(v.x,h0,l0); split_bf16(v.y,h1,l1);
    split_bf16(v.z,h2,l2); split_bf16(v.w,h3,l3);
    __nv_bfloat16* Pr = P + row * (size_t)(2 * NIN);
    *(uint2*)(Pr + blk*64 + w)      = make_uint2(pack2(h0,h1), pack2(h2,h3));
    *(uint2*)(Pr + blk*64 + 32 + w) = make_uint2(pack2(l0,l1), pack2(l2,l3));
}

// W [E][K][N] f32 -> Wp [E][N][K/32][64] (transpose + split)
__global__ __launch_bounds__(256)
void transpose_split_kernel(const float* __restrict__ W, __nv_bfloat16* __restrict__ Wp,
                            int K, int N)
{
    __shared__ float s[32][257];
    const int tid = threadIdx.x;
    const int e = blockIdx.z, n0 = blockIdx.x * 256, k0 = blockIdx.y * 32;
    const float* We = W + (size_t)e * K * N;
    for (int r = 0; r < 32; r++)
        s[r][tid] = We[(size_t)(k0 + r) * N + n0 + tid];
    __syncthreads();
    __nv_bfloat16 buf[64];
    #pragma unroll
    for (int r = 0; r < 32; r++) {
        __nv_bfloat16 h, l;
        split_bf16(s[r][tid], h, l);
        buf[r] = h; buf[32 + r] = l;
    }
    const size_t off = (((size_t)e * N + n0 + tid) * (size_t)(K >> 5) + (k0 >> 5)) * 64;
    uint4* dst = (uint4*)(Wp + off);
    const uint4* src = (const uint4*)buf;
    #pragma unroll
    for (int j = 0; j < 8; j++) dst[j] = src[j];
}

// ---------------- mma.sync bf16x3 GEMM ----------------
// C[e][M,N] = Ap([e]) @ Bp[e]^T + bias[e]. Packed rows of 2K bf16 (4K bytes).
// Block 128x128, 8 warps (2 M x 4 N), warp 64x32, BK=32, 3-stage cp.async.
#define GSMEM (3 * 32768)

template<bool A_EXP>
__global__ void __launch_bounds__(256)
gemm_mma_bf16x3(const __nv_bfloat16* __restrict__ Ap,
                const __nv_bfloat16* __restrict__ Bp,
                const float* __restrict__ bias, float* __restrict__ C,
                int M, int N, int K)
{
    extern __shared__ char smem[];
    const uint32_t sb = smem_u32(smem);
    const int tid = threadIdx.x;
    const int lane = tid & 31, wid = tid >> 5;
    const int wm = wid & 1, wn = wid >> 1;
    const int e = blockIdx.z;
    const int row0 = blockIdx.y * 128, col0 = blockIdx.x * 128;
    const size_t rowbytes = (size_t)K * 4;
    const char* Ab = (const char*)Ap + ((A_EXP ? (size_t)e * M : (size_t)0) + row0) * rowbytes;
    const char* Bb = (const char*)Bp + ((size_t)e * N + col0) * rowbytes;
    const int S = K >> 5;

    auto load_stage = [&](int s) {
        const int buf = s % 3;
        const uint32_t a0 = sb + (uint32_t)buf * 32768u, b0 = a0 + 16384u;
        #pragma unroll
        for (int k = 0; k < 4; k++) {
            const int c = tid + k * 256;
            const int row = c >> 3, cb = (c & 7) * 16;
            uint32_t off = (uint32_t)(row * 128 + cb);
            off ^= (off >> 3) & 0x70;
            const char* src = Ab + (size_t)row * rowbytes + (size_t)s * 128 + cb;
            asm volatile("cp.async.cg.shared.global [%0], [%1], 16;"
                         :: "r"(a0 + off), "l"(src));
        }
        #pragma unroll
        for (int k = 0; k < 4; k++) {
            const int c = tid + k * 256;
            const int row = c >> 3, cb = (c & 7) * 16;
            uint32_t off = (uint32_t)(row * 128 + cb);
            off ^= (off >> 3) & 0x70;
            const char* src = Bb + (size_t)row * rowbytes + (size_t)s * 128 + cb;
            asm volatile("cp.async.cg.shared.global [%0], [%1], 16;"
                         :: "r"(b0 + off), "l"(src));
        }
        asm volatile("cp.async.commit_group;" ::: "memory");
    };

    float acc[4][4][4] = {};

    load_stage(0);
    load_stage(1);

    for (int kb = 0; kb < S; kb++) {
        asm volatile("cp.async.wait_group 1;" ::: "memory");
        __syncthreads();
        if (kb + 2 < S) load_stage(kb + 2);
        else asm volatile("cp.async.commit_group;" ::: "memory");

        const int buf = kb % 3;
        const uint32_t asA = sb + (uint32_t)buf * 32768u;
        const uint32_t asB = asA + 16384u;
        const int arow = wm * 64 + (lane & 15);
        const int brow_l = ((lane >> 4) << 3) + (lane & 7);

        #pragma unroll
        for (int pass = 0; pass < 3; pass++) {
            const int ao = (pass == 1) ? 64 : 0;   // A half: hi, lo, hi
            const int bo = (pass == 2) ? 64 : 0;   // B half: hi, hi, lo
            #pragma unroll
            for (int h = 0; h < 2; h++) {
                uint32_t a[4][4], b[2][4];
                const int acol = ao + h * 32 + ((lane >> 4) << 4);
                #pragma unroll
                for (int i = 0; i < 4; i++) {
                    uint32_t byt = (uint32_t)((arow + i * 16) * 128 + acol);
                    byt ^= (byt >> 3) & 0x70;
                    asm volatile(
                        "ldmatrix.sync.aligned.m8n8.x4.shared.b16 {%0,%1,%2,%3}, [%4];"
                        : "=r"(a[i][0]), "=r"(a[i][1]), "=r"(a[i][2]), "=r"(a[i][3])
                        : "r"(asA + byt));
                }
                const int bcol = bo + h * 32 + (((lane >> 3) & 1) << 4);
                #pragma unroll
                for (int j2 = 0; j2 < 2; j2++) {
                    const int brow = wn * 32 + j2 * 16 + brow_l;
                    uint32_t byt = (uint32_t)(brow * 128 + bcol);
                    byt ^= (byt >> 3) & 0x70;
                    asm volatile(
                        "ldmatrix.sync.aligned.m8n8.x4.shared.b16 {%0,%1,%2,%3}, [%4];"
                        : "=r"(b[j2][0]), "=r"(b[j2][1]), "=r"(b[j2][2]), "=r"(b[j2][3])
                        : "r"(asB + byt));
                }
                #pragma unroll
                for (int i = 0; i < 4; i++)
                    #pragma unroll
                    for (int j2 = 0; j2 < 2; j2++)
                        #pragma unroll
                        for (int t = 0; t < 2; t++) {
                            float* d = acc[i][j2 * 2 + t];
                            asm volatile(
                                "mma.sync.aligned.m16n8k16.row.col.f32.bf16.bf16.f32 "
                                "{%0,%1,%2,%3},{%4,%5,%6,%7},{%8,%9},{%0,%1,%2,%3};"
                                : "+f"(d[0]), "+f"(d[1]), "+f"(d[2]), "+f"(d[3])
                                : "r"(a[i][0]), "r"(a[i][1]), "r"(a[i][2]), "r"(a[i][3]),
                                  "r"(b[j2][2 * t]), "r"(b[j2][2 * t + 1]));
                        }
            }
        }
        __syncthreads();
    }

    // Epilogue: direct global write + bias
    const float* bz = bias + (size_t)e * N + col0 + wn * 32;
    float* Cb = C + (size_t)e * M * N + (size_t)(row0 + wm * 64) * N + col0 + wn * 32;
    const int r = lane >> 2, cc = (lane & 3) * 2;
    #pragma unroll
    for (int i = 0; i < 4; i++)
        #pragma unroll
        for (int j = 0; j < 4; j++) {
            const int col = j * 8 + cc;
            const float b0v = bz[col], b1v = bz[col + 1];
            float2 v0 = make_float2(acc[i][j][0] + b0v, acc[i][j][1] + b1v);
            float2 v1 = make_float2(acc[i][j][2] + b0v, acc[i][j][3] + b1v);
            *(float2*)(Cb + (size_t)(i * 16 + r) * N + col) = v0;
            *(float2*)(Cb + (size_t)(i * 16 + r + 8) * N + col) = v1;
        }
}

// ---------------- LN + GELU + pack ----------------
__global__ __launch_bounds__(256)
void ln_gelu_pack(const float* __restrict__ H, __nv_bfloat16* __restrict__ Hp,
                  const float* __restrict__ gamma, const float* __restrict__ beta)
{
    const size_t row = blockIdx.x;
    const int e = (int)(row / NB);
    const int tid = threadIdx.x;
    const float4* xr = (const float4*)(H + row * (size_t)NHID);
    const float4* gp = (const float4*)(gamma + (size_t)e * NHID);
    const float4* bp = (const float4*)(beta  + (size_t)e * NHID);

    float4 v[4];
    float s = 0.f, s2 = 0.f;
    #pragma unroll
    for (int i = 0; i < 4; i++) {
        v[i] = xr[i * 256 + tid];
        s  += v[i].x + v[i].y + v[i].z + v[i].w;
        s2 += v[i].x*v[i].x + v[i].y*v[i].y + v[i].z*v[i].z + v[i].w*v[i].w;
    }
    block_sum2(s, s2);
    const float mean = s * (1.0f / NHID);
    const float rstd = rsqrtf(s2 * (1.0f / NHID) - mean * mean + EPS);

    __nv_bfloat16* Pr = Hp + row * (size_t)(2 * NHID);
    #pragma unroll
    for (int i = 0; i < 4; i++) {
        const int idx = i * 256 + tid;
        const float4 g4 = gp[idx], b4 = bp[idx];
        float4 a;
        a.x = gelu_exact((v[i].x - mean) * rstd * g4.x + b4.x);
        a.y = gelu_exact((v[i].y - mean) * rstd * g4.y + b4.y);
        a.z = gelu_exact((v[i].z - mean) * rstd * g4.z + b4.z);
        a.w = gelu_exact((v[i].w - mean) * rstd * g4.w + b4.w);
        __nv_bfloat16 h0,h1,h2,h3,l0,l1,l2,l3;
        split_bf16(a.x,h0,l0); split_bf16(a.y,h1,l1);
        split_bf16(a.z,h2,l2); split_bf16(a.w,h3,l3);
        const int col = idx * 4, blk = col >> 5, w = col & 31;
        *(uint2*)(Pr + blk*64 + w)      = make_uint2(pack2(h0,h1), pack2(h2,h3));
        *(uint2*)(Pr + blk*64 + 32 + w) = make_uint2(pack2(l0,l1), pack2(l2,l3));
    }
}

// ---------------- final LN+GELU+weighted combine ----------------
__global__ __launch_bounds__(256)
void combine_kernel(const float* __restrict__ w,
                    const float* __restrict__ g2, const float* __restrict__ be2,
                    float* __restrict__ out)
{
    const int b = blockIdx.x, tid = threadIdx.x;
    float acc[4] = {0.f, 0.f, 0.f, 0.f};
    for (int e = 0; e < NE; e++) {
        const float* yr = g_Y + ((size_t)e * NB + b) * NOUT;
        float vv[4];
        float s = 0.f, s2 = 0.f;
        #pragma unroll
        for (int i = 0; i < 4; i++) {
            vv[i] = yr[tid + i * 256];
            s += vv[i]; s2 += vv[i] * vv[i];
        }
        block_sum2(s, s2);
        const float mean = s * (1.0f / NOUT);
        const float rstd = rsqrtf(s2 * (1.0f / NOUT) - mean * mean + EPS);
        const float we = w[(size_t)b * NE + e];
        #pragma unroll
        for (int i = 0; i < 4; i++) {
            const int o = tid + i * 256;
            const float val = (vv[i] - mean) * rstd * g2[(size_t)e * NOUT + o]
                              + be2[(size_t)e * NOUT + o];
            acc[i] += we * gelu_exact(val);
        }
    }
    #pragma unroll
    for (int i = 0; i < 4; i++)
        out[(size_t)b * NOUT + tid + i * 256] = acc[i];
}

// ---------------------------------------------------------------------------
extern "C" void kernel_launch(void* const* d_in, const int* in_sizes, int n_in,
                              void* d_out, int out_size)
{
    const float* x   = (const float*)d_in[0];
    const float* wts = (const float*)d_in[1];
    const float* W1  = (const float*)d_in[2];
    const float* b1  = (const float*)d_in[3];
    const float* g1  = (const float*)d_in[4];
    const float* be1 = (const float*)d_in[5];
    const float* W2  = (const float*)d_in[6];
    const float* b2  = (const float*)d_in[7];
    const float* g2  = (const float*)d_in[8];
    const float* be2 = (const float*)d_in[9];
    float* out = (float*)d_out;

    __nv_bfloat16 *Px, *Wp1, *Wp2, *Hp;
    float *H, *Y;
    cudaGetSymbolAddress((void**)&Px,  g_Px);
    cudaGetSymbolAddress((void**)&Wp1, g_Wp1);
    cudaGetSymbolAddress((void**)&Wp2, g_Wp2);
    cudaGetSymbolAddress((void**)&H,   g_H);
    cudaGetSymbolAddress((void**)&Hp,  g_Hp);
    cudaGetSymbolAddress((void**)&Y,   g_Y);

    cudaFuncSetAttribute(gemm_mma_bf16x3<false>,
                         cudaFuncAttributeMaxDynamicSharedMemorySize, GSMEM);
    cudaFuncSetAttribute(gemm_mma_bf16x3<true>,
                         cudaFuncAttributeMaxDynamicSharedMemorySize, GSMEM);

    dim3 blk(256);
    split_x_kernel<<<NB, blk>>>(x, Px);
    transpose_split_kernel<<<dim3(NHID/256, NIN/32, NE), blk>>>(W1, Wp1, NIN, NHID);
    transpose_split_kernel<<<dim3(NOUT/256, NHID/32, NE), blk>>>(W2, Wp2, NHID, NOUT);

    gemm_mma_bf16x3<false><<<dim3(NHID/128, NB/128, NE), blk, GSMEM>>>(
        Px, Wp1, b1, H, NB, NHID, NIN);

    ln_gelu_pack<<<NE * NB, blk>>>(H, Hp, g1, be1);

    gemm_mma_bf16x3<true><<<dim3(NOUT/128, NB/128, NE), blk, GSMEM>>>(
        Hp, Wp2, b2, Y, NB, NOUT, NHID);

    combine_kernel<<<NB, blk>>>(wts, g2, be2, out);
}

// round 6
// speedup vs baseline: 7.6937x; 2.6975x over previous
#include <cuda_runtime.h>
#include <cuda_fp16.h>
#include <math.h>
#include <stdint.h>

#define NB   8192
#define NIN  1024
#define NHID 4096
#define NOUT 1024
#define NE   8
#define EPS  1e-5f

__device__ __align__(256) __half g_Xh [(size_t)NB * NIN];
__device__ __align__(256) __half g_Wh1[(size_t)NE * NHID * NIN];   // [E][N][K]
__device__ __align__(256) __half g_Wh2[(size_t)NE * NOUT * NHID];  // [E][N][K]
__device__ __align__(256) float  g_H  [(size_t)NE * NB * NHID];
__device__ __align__(256) __half g_Hh [(size_t)NE * NB * NHID];
__device__ __align__(256) float  g_Y  [(size_t)NE * NB * NOUT];

__device__ __forceinline__ uint32_t smem_u32(const void* p) {
    return (uint32_t)__cvta_generic_to_shared(p);
}
__device__ __forceinline__ float gelu_exact(float v) {
    return 0.5f * v * (1.0f + erff(v * 0.70710678118654752f));
}
__device__ __forceinline__ void block_sum2(float& s, float& s2) {
    __shared__ float sh[2][8];
    #pragma unroll
    for (int o = 16; o > 0; o >>= 1) {
        s  += __shfl_xor_sync(0xffffffffu, s,  o);
        s2 += __shfl_xor_sync(0xffffffffu, s2, o);
    }
    const int w = threadIdx.x >> 5, lane = threadIdx.x & 31;
    if (lane == 0) { sh[0][w] = s; sh[1][w] = s2; }
    __syncthreads();
    float t = 0.f, t2 = 0.f;
    #pragma unroll
    for (int i = 0; i < 8; i++) { t += sh[0][i]; t2 += sh[1][i]; }
    s = t; s2 = t2;
    __syncthreads();
}
__device__ __forceinline__ uint32_t packh2(float a, float b) {
    __half2 h = __floats2half2_rn(a, b);
    return *reinterpret_cast<uint32_t*>(&h);
}

// ---------------- prep kernels ----------------
// x [NB][NIN] f32 -> Xh fp16
__global__ __launch_bounds__(256)
void cast_x_kernel(const float* __restrict__ X, __half* __restrict__ P)
{
    const size_t row = blockIdx.x;
    const int tid = threadIdx.x;
    const float4 v = ((const float4*)(X + row * NIN))[tid];
    uint2 o = make_uint2(packh2(v.x, v.y), packh2(v.z, v.w));
    *(uint2*)(P + row * NIN + tid * 4) = o;
}

// W [E][K][N] f32 -> Wh [E][N][K] fp16 (transpose + cast)
__global__ __launch_bounds__(256)
void transpose_cast_kernel(const float* __restrict__ W, __half* __restrict__ Wh,
                           int K, int N)
{
    __shared__ float s[32][257];
    const int tid = threadIdx.x;
    const int e = blockIdx.z, n0 = blockIdx.x * 256, k0 = blockIdx.y * 32;
    const float* We = W + (size_t)e * K * N;
    for (int r = 0; r < 32; r++)
        s[r][tid] = We[(size_t)(k0 + r) * N + n0 + tid];
    __syncthreads();
    uint32_t buf[16];
    #pragma unroll
    for (int r = 0; r < 32; r += 2)
        buf[r >> 1] = packh2(s[r][tid], s[r + 1][tid]);
    __half* dst = Wh + ((size_t)e * N + n0 + tid) * (size_t)K + k0;
    #pragma unroll
    for (int j = 0; j < 4; j++)
        *(uint4*)(dst + j * 8) = ((const uint4*)buf)[j];
}

// ---------------- fp16 mma.sync GEMM ----------------
// C[e][M,N] = A([e]) @ B[e]^T + bias[e].  A,B: fp16 K-major rows.
// CTA 128x256, 8 warps (2Mx4N), warp 64x64, BK=64, 3-stage cp.async.
#define STG_A   16384
#define STG_B   32768
#define STG     (STG_A + STG_B)
#define GSMEM   (3 * STG)

template<bool A_EXP>
__global__ void __launch_bounds__(256, 1)
gemm_f16(const __half* __restrict__ Ap, const __half* __restrict__ Bp,
         const float* __restrict__ bias, float* __restrict__ C,
         int M, int N, int K)
{
    extern __shared__ char smem[];
    const uint32_t sb = smem_u32(smem);
    const int tid = threadIdx.x;
    const int lane = tid & 31, wid = tid >> 5;
    const int wm = wid & 1, wn = wid >> 1;
    const int e = blockIdx.z;
    const int row0 = blockIdx.y * 128, col0 = blockIdx.x * 256;
    const size_t rowbytes = (size_t)K * 2;
    const char* Ab = (const char*)Ap + ((A_EXP ? (size_t)e * M : (size_t)0) + row0) * rowbytes;
    const char* Bb = (const char*)Bp + ((size_t)e * N + col0) * rowbytes;
    const int S = K >> 6;

    auto load_stage = [&](int s) {
        const int buf = s % 3;
        const uint32_t a0 = sb + (uint32_t)buf * STG, b0 = a0 + STG_A;
        #pragma unroll
        for (int k = 0; k < 4; k++) {          // A: 1024 16B chunks
            const int c = tid + k * 256;
            const int row = c >> 3, cb = (c & 7) * 16;
            uint32_t off = (uint32_t)(row * 128 + cb);
            off ^= (off >> 3) & 0x70;
            const char* src = Ab + (size_t)row * rowbytes + (size_t)s * 128 + cb;
            asm volatile("cp.async.cg.shared.global [%0], [%1], 16;"
                         :: "r"(a0 + off), "l"(src));
        }
        #pragma unroll
        for (int k = 0; k < 8; k++) {          // B: 2048 16B chunks
            const int c = tid + k * 256;
            const int row = c >> 3, cb = (c & 7) * 16;
            uint32_t off = (uint32_t)(row * 128 + cb);
            off ^= (off >> 3) & 0x70;
            const char* src = Bb + (size_t)row * rowbytes + (size_t)s * 128 + cb;
            asm volatile("cp.async.cg.shared.global [%0], [%1], 16;"
                         :: "r"(b0 + off), "l"(src));
        }
        asm volatile("cp.async.commit_group;" ::: "memory");
    };

    float acc[4][8][4] = {};

    load_stage(0);
    load_stage(1);

    const int arow = wm * 64 + (lane & 15);
    const int acolsel = (lane >> 4) << 4;
    const int brow_l = ((lane >> 4) << 3) + (lane & 7);
    const int bcolsel = ((lane >> 3) & 1) << 4;

    for (int kb = 0; kb < S; kb++) {
        asm volatile("cp.async.wait_group 1;" ::: "memory");
        __syncthreads();
        if (kb + 2 < S) load_stage(kb + 2);
        else asm volatile("cp.async.commit_group;" ::: "memory");

        const int buf = kb % 3;
        const uint32_t asA = sb + (uint32_t)buf * STG;
        const uint32_t asB = asA + STG_A;

        #pragma unroll
        for (int h = 0; h < 4; h++) {          // 4 x k16 per 128B k-block
            uint32_t a[4][4], b[4][4];
            const int acol = h * 32 + acolsel;
            #pragma unroll
            for (int i = 0; i < 4; i++) {
                uint32_t byt = (uint32_t)((arow + i * 16) * 128 + acol);
                byt ^= (byt >> 3) & 0x70;
                asm volatile(
                    "ldmatrix.sync.aligned.m8n8.x4.shared.b16 {%0,%1,%2,%3}, [%4];"
                    : "=r"(a[i][0]), "=r"(a[i][1]), "=r"(a[i][2]), "=r"(a[i][3])
                    : "r"(asA + byt));
            }
            const int bcol = h * 32 + bcolsel;
            #pragma unroll
            for (int j2 = 0; j2 < 4; j2++) {
                const int brow = wn * 64 + j2 * 16 + brow_l;
                uint32_t byt = (uint32_t)(brow * 128 + bcol);
                byt ^= (byt >> 3) & 0x70;
                asm volatile(
                    "ldmatrix.sync.aligned.m8n8.x4.shared.b16 {%0,%1,%2,%3}, [%4];"
                    : "=r"(b[j2][0]), "=r"(b[j2][1]), "=r"(b[j2][2]), "=r"(b[j2][3])
                    : "r"(asB + byt));
            }
            #pragma unroll
            for (int i = 0; i < 4; i++)
                #pragma unroll
                for (int j2 = 0; j2 < 4; j2++)
                    #pragma unroll
                    for (int t = 0; t < 2; t++) {
                        float* d = acc[i][j2 * 2 + t];
                        asm volatile(
                            "mma.sync.aligned.m16n8k16.row.col.f32.f16.f16.f32 "
                            "{%0,%1,%2,%3},{%4,%5,%6,%7},{%8,%9},{%0,%1,%2,%3};"
                            : "+f"(d[0]), "+f"(d[1]), "+f"(d[2]), "+f"(d[3])
                            : "r"(a[i][0]), "r"(a[i][1]), "r"(a[i][2]), "r"(a[i][3]),
                              "r"(b[j2][2 * t]), "r"(b[j2][2 * t + 1]));
                    }
        }
        __syncthreads();
    }

    // Epilogue: warp owns 64x64 at (row0 + wm*64, col0 + wn*64)
    const float* bz = bias + (size_t)e * N + col0 + wn * 64;
    float* Cb = C + (size_t)e * M * N + (size_t)(row0 + wm * 64) * N + col0 + wn * 64;
    const int r = lane >> 2, cc = (lane & 3) * 2;
    #pragma unroll
    for (int i = 0; i < 4; i++)
        #pragma unroll
        for (int j = 0; j < 8; j++) {
            const int col = j * 8 + cc;
            const float b0v = bz[col], b1v = bz[col + 1];
            float2 v0 = make_float2(acc[i][j][0] + b0v, acc[i][j][1] + b1v);
            float2 v1 = make_float2(acc[i][j][2] + b0v, acc[i][j][3] + b1v);
            *(float2*)(Cb + (size_t)(i * 16 + r) * N + col) = v0;
            *(float2*)(Cb + (size_t)(i * 16 + r + 8) * N + col) = v1;
        }
}

// ---------------- LN + GELU -> fp16 ----------------
__global__ __launch_bounds__(256)
void ln_gelu_f16(const float* __restrict__ H, __half* __restrict__ Hh,
                 const float* __restrict__ gamma, const float* __restrict__ beta)
{
    const size_t row = blockIdx.x;
    const int e = (int)(row / NB);
    const int tid = threadIdx.x;
    const float4* xr = (const float4*)(H + row * (size_t)NHID);
    const float4* gp = (const float4*)(gamma + (size_t)e * NHID);
    const float4* bp = (const float4*)(beta  + (size_t)e * NHID);

    float4 v[4];
    float s = 0.f, s2 = 0.f;
    #pragma unroll
    for (int i = 0; i < 4; i++) {
        v[i] = xr[i * 256 + tid];
        s  += v[i].x + v[i].y + v[i].z + v[i].w;
        s2 += v[i].x*v[i].x + v[i].y*v[i].y + v[i].z*v[i].z + v[i].w*v[i].w;
    }
    block_sum2(s, s2);
    const float mean = s * (1.0f / NHID);
    const float rstd = rsqrtf(s2 * (1.0f / NHID) - mean * mean + EPS);

    __half* Pr = Hh + row * (size_t)NHID;
    #pragma unroll
    for (int i = 0; i < 4; i++) {
        const int idx = i * 256 + tid;
        const float4 g4 = gp[idx], b4 = bp[idx];
        float a0 = gelu_exact((v[i].x - mean) * rstd * g4.x + b4.x);
        float a1 = gelu_exact((v[i].y - mean) * rstd * g4.y + b4.y);
        float a2 = gelu_exact((v[i].z - mean) * rstd * g4.z + b4.z);
        float a3 = gelu_exact((v[i].w - mean) * rstd * g4.w + b4.w);
        *(uint2*)(Pr + idx * 4) = make_uint2(packh2(a0, a1), packh2(a2, a3));
    }
}

// ---------------- final LN+GELU+weighted combine ----------------
__global__ __launch_bounds__(256)
void combine_kernel(const float* __restrict__ w,
                    const float* __restrict__ g2, const float* __restrict__ be2,
                    float* __restrict__ out)
{
    const int b = blockIdx.x, tid = threadIdx.x;
    float acc[4] = {0.f, 0.f, 0.f, 0.f};
    for (int e = 0; e < NE; e++) {
        const float* yr = g_Y + ((size_t)e * NB + b) * NOUT;
        float vv[4];
        float s = 0.f, s2 = 0.f;
        #pragma unroll
        for (int i = 0; i < 4; i++) {
            vv[i] = yr[tid + i * 256];
            s += vv[i]; s2 += vv[i] * vv[i];
        }
        block_sum2(s, s2);
        const float mean = s * (1.0f / NOUT);
        const float rstd = rsqrtf(s2 * (1.0f / NOUT) - mean * mean + EPS);
        const float we = w[(size_t)b * NE + e];
        #pragma unroll
        for (int i = 0; i < 4; i++) {
            const int o = tid + i * 256;
            const float val = (vv[i] - mean) * rstd * g2[(size_t)e * NOUT + o]
                              + be2[(size_t)e * NOUT + o];
            acc[i] += we * gelu_exact(val);
        }
    }
    #pragma unroll
    for (int i = 0; i < 4; i++)
        out[(size_t)b * NOUT + tid + i * 256] = acc[i];
}

// ---------------------------------------------------------------------------
extern "C" void kernel_launch(void* const* d_in, const int* in_sizes, int n_in,
                              void* d_out, int out_size)
{
    const float* x   = (const float*)d_in[0];
    const float* wts = (const float*)d_in[1];
    const float* W1  = (const float*)d_in[2];
    const float* b1  = (const float*)d_in[3];
    const float* g1  = (const float*)d_in[4];
    const float* be1 = (const float*)d_in[5];
    const float* W2  = (const float*)d_in[6];
    const float* b2  = (const float*)d_in[7];
    const float* g2  = (const float*)d_in[8];
    const float* be2 = (const float*)d_in[9];
    float* out = (float*)d_out;

    __half *Xh, *Wh1, *Wh2, *Hh;
    float *H, *Y;
    cudaGetSymbolAddress((void**)&Xh,  g_Xh);
    cudaGetSymbolAddress((void**)&Wh1, g_Wh1);
    cudaGetSymbolAddress((void**)&Wh2, g_Wh2);
    cudaGetSymbolAddress((void**)&H,   g_H);
    cudaGetSymbolAddress((void**)&Hh,  g_Hh);
    cudaGetSymbolAddress((void**)&Y,   g_Y);

    cudaFuncSetAttribute(gemm_f16<false>,
                         cudaFuncAttributeMaxDynamicSharedMemorySize, GSMEM);
    cudaFuncSetAttribute(gemm_f16<true>,
                         cudaFuncAttributeMaxDynamicSharedMemorySize, GSMEM);

    dim3 blk(256);
    cast_x_kernel<<<NB, blk>>>(x, Xh);
    transpose_cast_kernel<<<dim3(NHID/256, NIN/32, NE), blk>>>(W1, Wh1, NIN, NHID);
    transpose_cast_kernel<<<dim3(NOUT/256, NHID/32, NE), blk>>>(W2, Wh2, NHID, NOUT);

    gemm_f16<false><<<dim3(NHID/256, NB/128, NE), blk, GSMEM>>>(
        Xh, Wh1, b1, H, NB, NHID, NIN);

    ln_gelu_f16<<<NE * NB, blk>>>(H, Hh, g1, be1);

    gemm_f16<true><<<dim3(NOUT/256, NB/128, NE), blk, GSMEM>>>(
        Hh, Wh2, b2, Y, NB, NOUT, NHID);

    combine_kernel<<<NB, blk>>>(wts, g2, be2, out);
}

// round 7
// speedup vs baseline: 7.8827x; 1.0246x over previous
#include <cuda_runtime.h>
#include <cuda_fp16.h>
#include <math.h>
#include <stdint.h>

#define NB   8192
#define NIN  1024
#define NHID 4096
#define NOUT 1024
#define NE   8
#define EPS  1e-5f

__device__ __align__(256) __half g_Xh [(size_t)NB * NIN];
__device__ __align__(256) __half g_Wh1[(size_t)NE * NHID * NIN];   // [E][N][K]
__device__ __align__(256) __half g_Wh2[(size_t)NE * NOUT * NHID];  // [E][N][K]
__device__ __align__(256) __half g_Hh [(size_t)NE * NB * NHID];    // pre-LN then act
__device__ __align__(256) float  g_Y  [(size_t)NE * NB * NOUT];

__device__ __forceinline__ uint32_t smem_u32(const void* p) {
    return (uint32_t)__cvta_generic_to_shared(p);
}
__device__ __forceinline__ float gelu_exact(float v) {
    return 0.5f * v * (1.0f + erff(v * 0.70710678118654752f));
}
__device__ __forceinline__ void block_sum2(float& s, float& s2) {
    __shared__ float sh[2][8];
    #pragma unroll
    for (int o = 16; o > 0; o >>= 1) {
        s  += __shfl_xor_sync(0xffffffffu, s,  o);
        s2 += __shfl_xor_sync(0xffffffffu, s2, o);
    }
    const int w = threadIdx.x >> 5, lane = threadIdx.x & 31;
    if (lane == 0) { sh[0][w] = s; sh[1][w] = s2; }
    __syncthreads();
    float t = 0.f, t2 = 0.f;
    #pragma unroll
    for (int i = 0; i < 8; i++) { t += sh[0][i]; t2 += sh[1][i]; }
    s = t; s2 = t2;
    __syncthreads();
}
__device__ __forceinline__ uint32_t packh2(float a, float b) {
    __half2 h = __floats2half2_rn(a, b);
    return *reinterpret_cast<uint32_t*>(&h);
}

// ---------------- prep kernels ----------------
__global__ __launch_bounds__(256)
void cast_x_kernel(const float* __restrict__ X, __half* __restrict__ P)
{
    const size_t row = blockIdx.x;
    const int tid = threadIdx.x;
    const float4 v = ((const float4*)(X + row * NIN))[tid];
    *(uint2*)(P + row * NIN + tid * 4) = make_uint2(packh2(v.x, v.y), packh2(v.z, v.w));
}

// W [E][K][N] f32 -> Wh [E][N][K] fp16 (transpose + cast)
__global__ __launch_bounds__(256)
void transpose_cast_kernel(const float* __restrict__ W, __half* __restrict__ Wh,
                           int K, int N)
{
    __shared__ float s[32][257];
    const int tid = threadIdx.x;
    const int e = blockIdx.z, n0 = blockIdx.x * 256, k0 = blockIdx.y * 32;
    const float* We = W + (size_t)e * K * N;
    for (int r = 0; r < 32; r++)
        s[r][tid] = We[(size_t)(k0 + r) * N + n0 + tid];
    __syncthreads();
    uint32_t buf[16];
    #pragma unroll
    for (int r = 0; r < 32; r += 2)
        buf[r >> 1] = packh2(s[r][tid], s[r + 1][tid]);
    __half* dst = Wh + ((size_t)e * N + n0 + tid) * (size_t)K + k0;
    #pragma unroll
    for (int j = 0; j < 4; j++)
        *(uint4*)(dst + j * 8) = ((const uint4*)buf)[j];
}

// ---------------- fp16 mma.sync GEMM ----------------
// C[e][M,N] = A([e]) @ B[e]^T + bias[e].  A,B fp16 K-major rows.
// CTA 128x128, 8 warps (2M x 4N), warp 64x32, BK=64, 3-stage cp.async,
// 2 CTAs/SM. OUT_F16 selects fp16 vs fp32 output.
#define STG_A   16384
#define STG_B   16384
#define STG     (STG_A + STG_B)
#define GSMEM   (3 * STG)

template<bool A_EXP, bool OUT_F16>
__global__ void __launch_bounds__(256, 2)
gemm_f16(const __half* __restrict__ Ap, const __half* __restrict__ Bp,
         const float* __restrict__ bias, void* __restrict__ Cv,
         int M, int N, int K)
{
    extern __shared__ char smem[];
    const uint32_t sb = smem_u32(smem);
    const int tid = threadIdx.x;
    const int lane = tid & 31, wid = tid >> 5;
    const int wm = wid & 1, wn = wid >> 1;
    const int e = blockIdx.z;
    const int row0 = blockIdx.y * 128, col0 = blockIdx.x * 128;
    const size_t rowbytes = (size_t)K * 2;
    const char* Ab = (const char*)Ap + ((A_EXP ? (size_t)e * M : (size_t)0) + row0) * rowbytes;
    const char* Bb = (const char*)Bp + ((size_t)e * N + col0) * rowbytes;
    const int S = K >> 6;

    auto load_stage = [&](int s) {
        const int buf = s % 3;
        const uint32_t a0 = sb + (uint32_t)buf * STG, b0 = a0 + STG_A;
        #pragma unroll
        for (int k = 0; k < 4; k++) {
            const int c = tid + k * 256;
            const int row = c >> 3, cb = (c & 7) * 16;
            uint32_t off = (uint32_t)(row * 128 + cb);
            off ^= (off >> 3) & 0x70;
            asm volatile("cp.async.cg.shared.global [%0], [%1], 16;"
                         :: "r"(a0 + off),
                            "l"(Ab + (size_t)row * rowbytes + (size_t)s * 128 + cb));
        }
        #pragma unroll
        for (int k = 0; k < 4; k++) {
            const int c = tid + k * 256;
            const int row = c >> 3, cb = (c & 7) * 16;
            uint32_t off = (uint32_t)(row * 128 + cb);
            off ^= (off >> 3) & 0x70;
            asm volatile("cp.async.cg.shared.global [%0], [%1], 16;"
                         :: "r"(b0 + off),
                            "l"(Bb + (size_t)row * rowbytes + (size_t)s * 128 + cb));
        }
        asm volatile("cp.async.commit_group;" ::: "memory");
    };

    float acc[4][4][4] = {};

    load_stage(0);
    load_stage(1);

    const int arow = wm * 64 + (lane & 15);
    const int acolsel = (lane >> 4) << 4;
    const int brow_l = ((lane >> 4) << 3) + (lane & 7);
    const int bcolsel = ((lane >> 3) & 1) << 4;

    for (int kb = 0; kb < S; kb++) {
        asm volatile("cp.async.wait_group 1;" ::: "memory");
        __syncthreads();
        if (kb + 2 < S) load_stage(kb + 2);
        else asm volatile("cp.async.commit_group;" ::: "memory");

        const int buf = kb % 3;
        const uint32_t asA = sb + (uint32_t)buf * STG;
        const uint32_t asB = asA + STG_A;

        #pragma unroll
        for (int h = 0; h < 4; h++) {
            uint32_t a[4][4], b[2][4];
            const int acol = h * 32 + acolsel;
            #pragma unroll
            for (int i = 0; i < 4; i++) {
                uint32_t byt = (uint32_t)((arow + i * 16) * 128 + acol);
                byt ^= (byt >> 3) & 0x70;
                asm volatile(
                    "ldmatrix.sync.aligned.m8n8.x4.shared.b16 {%0,%1,%2,%3}, [%4];"
                    : "=r"(a[i][0]), "=r"(a[i][1]), "=r"(a[i][2]), "=r"(a[i][3])
                    : "r"(asA + byt));
            }
            const int bcol = h * 32 + bcolsel;
            #pragma unroll
            for (int j2 = 0; j2 < 2; j2++) {
                const int brow = wn * 32 + j2 * 16 + brow_l;
                uint32_t byt = (uint32_t)(brow * 128 + bcol);
                byt ^= (byt >> 3) & 0x70;
                asm volatile(
                    "ldmatrix.sync.aligned.m8n8.x4.shared.b16 {%0,%1,%2,%3}, [%4];"
                    : "=r"(b[j2][0]), "=r"(b[j2][1]), "=r"(b[j2][2]), "=r"(b[j2][3])
                    : "r"(asB + byt));
            }
            #pragma unroll
            for (int i = 0; i < 4; i++)
                #pragma unroll
                for (int j2 = 0; j2 < 2; j2++)
                    #pragma unroll
                    for (int t = 0; t < 2; t++) {
                        float* d = acc[i][j2 * 2 + t];
                        asm volatile(
                            "mma.sync.aligned.m16n8k16.row.col.f32.f16.f16.f32 "
                            "{%0,%1,%2,%3},{%4,%5,%6,%7},{%8,%9},{%0,%1,%2,%3};"
                            : "+f"(d[0]), "+f"(d[1]), "+f"(d[2]), "+f"(d[3])
                            : "r"(a[i][0]), "r"(a[i][1]), "r"(a[i][2]), "r"(a[i][3]),
                              "r"(b[j2][2 * t]), "r"(b[j2][2 * t + 1]));
                    }
        }
        __syncthreads();
    }

    // Epilogue: warp owns 64x32 at (row0 + wm*64, col0 + wn*32)
    const float* bz = bias + (size_t)e * N + col0 + wn * 32;
    const int r = lane >> 2, cc = (lane & 3) * 2;
    if (OUT_F16) {
        __half* Cb = (__half*)Cv + (size_t)e * M * N
                   + (size_t)(row0 + wm * 64) * N + col0 + wn * 32;
        #pragma unroll
        for (int i = 0; i < 4; i++)
            #pragma unroll
            for (int j = 0; j < 4; j++) {
                const int col = j * 8 + cc;
                const float b0v = bz[col], b1v = bz[col + 1];
                *(uint32_t*)(Cb + (size_t)(i * 16 + r) * N + col) =
                    packh2(acc[i][j][0] + b0v, acc[i][j][1] + b1v);
                *(uint32_t*)(Cb + (size_t)(i * 16 + r + 8) * N + col) =
                    packh2(acc[i][j][2] + b0v, acc[i][j][3] + b1v);
            }
    } else {
        float* Cb = (float*)Cv + (size_t)e * M * N
                  + (size_t)(row0 + wm * 64) * N + col0 + wn * 32;
        #pragma unroll
        for (int i = 0; i < 4; i++)
            #pragma unroll
            for (int j = 0; j < 4; j++) {
                const int col = j * 8 + cc;
                const float b0v = bz[col], b1v = bz[col + 1];
                *(float2*)(Cb + (size_t)(i * 16 + r) * N + col) =
                    make_float2(acc[i][j][0] + b0v, acc[i][j][1] + b1v);
                *(float2*)(Cb + (size_t)(i * 16 + r + 8) * N + col) =
                    make_float2(acc[i][j][2] + b0v, acc[i][j][3] + b1v);
            }
    }
}

// ---------------- in-place LN + GELU on fp16 rows ----------------
__global__ __launch_bounds__(256)
void ln_gelu_f16(__half* __restrict__ Hh,
                 const float* __restrict__ gamma, const float* __restrict__ beta)
{
    const size_t row = blockIdx.x;
    const int e = (int)(row / NB);
    const int tid = threadIdx.x;
    uint4* xr = (uint4*)(Hh + row * (size_t)NHID);   // 512 uint4 per row
    const float4* gp = (const float4*)(gamma + (size_t)e * NHID);
    const float4* bp = (const float4*)(beta  + (size_t)e * NHID);

    uint4 u[2];
    float v[16];
    float s = 0.f, s2 = 0.f;
    #pragma unroll
    for (int i = 0; i < 2; i++) {
        u[i] = xr[i * 256 + tid];
        const uint32_t* w32 = (const uint32_t*)&u[i];
        #pragma unroll
        for (int q = 0; q < 4; q++) {
            float2 f = __half22float2(*(const __half2*)&w32[q]);
            v[i * 8 + q * 2]     = f.x;
            v[i * 8 + q * 2 + 1] = f.y;
            s  += f.x + f.y;
            s2 += f.x * f.x + f.y * f.y;
        }
    }
    block_sum2(s, s2);
    const float mean = s * (1.0f / NHID);
    const float rstd = rsqrtf(s2 * (1.0f / NHID) - mean * mean + EPS);

    #pragma unroll
    for (int i = 0; i < 2; i++) {
        uint4 o;
        uint32_t* ow = (uint32_t*)&o;
        #pragma unroll
        for (int q = 0; q < 2; q++) {
            // element base index of this uint4: (i*256 + tid)*8
            const int eb = (i * 256 + tid) * 8 + q * 4;
            const float4 g4 = gp[eb >> 2], b4 = bp[eb >> 2];
            const float* vv = &v[i * 8 + q * 4];
            float a0 = gelu_exact((vv[0] - mean) * rstd * g4.x + b4.x);
            float a1 = gelu_exact((vv[1] - mean) * rstd * g4.y + b4.y);
            float a2 = gelu_exact((vv[2] - mean) * rstd * g4.z + b4.z);
            float a3 = gelu_exact((vv[3] - mean) * rstd * g4.w + b4.w);
            ow[q * 2]     = packh2(a0, a1);
            ow[q * 2 + 1] = packh2(a2, a3);
        }
        xr[i * 256 + tid] = o;
    }
}

// ---------------- final LN+GELU+weighted combine ----------------
__global__ __launch_bounds__(256)
void combine_kernel(const float* __restrict__ w,
                    const float* __restrict__ g2, const float* __restrict__ be2,
                    float* __restrict__ out)
{
    const int b = blockIdx.x, tid = threadIdx.x;
    float acc[4] = {0.f, 0.f, 0.f, 0.f};
    for (int e = 0; e < NE; e++) {
        const float* yr = g_Y + ((size_t)e * NB + b) * NOUT;
        float vv[4];
        float s = 0.f, s2 = 0.f;
        #pragma unroll
        for (int i = 0; i < 4; i++) {
            vv[i] = yr[tid + i * 256];
            s += vv[i]; s2 += vv[i] * vv[i];
        }
        block_sum2(s, s2);
        const float mean = s * (1.0f / NOUT);
        const float rstd = rsqrtf(s2 * (1.0f / NOUT) - mean * mean + EPS);
        const float we = w[(size_t)b * NE + e];
        #pragma unroll
        for (int i = 0; i < 4; i++) {
            const int o = tid + i * 256;
            const float val = (vv[i] - mean) * rstd * g2[(size_t)e * NOUT + o]
                              + be2[(size_t)e * NOUT + o];
            acc[i] += we * gelu_exact(val);
        }
    }
    #pragma unroll
    for (int i = 0; i < 4; i++)
        out[(size_t)b * NOUT + tid + i * 256] = acc[i];
}

// ---------------------------------------------------------------------------
extern "C" void kernel_launch(void* const* d_in, const int* in_sizes, int n_in,
                              void* d_out, int out_size)
{
    const float* x   = (const float*)d_in[0];
    const float* wts = (const float*)d_in[1];
    const float* W1  = (const float*)d_in[2];
    const float* b1  = (const float*)d_in[3];
    const float* g1  = (const float*)d_in[4];
    const float* be1 = (const float*)d_in[5];
    const float* W2  = (const float*)d_in[6];
    const float* b2  = (const float*)d_in[7];
    const float* g2  = (const float*)d_in[8];
    const float* be2 = (const float*)d_in[9];
    float* out = (float*)d_out;

    __half *Xh, *Wh1, *Wh2, *Hh;
    float *Y;
    cudaGetSymbolAddress((void**)&Xh,  g_Xh);
    cudaGetSymbolAddress((void**)&Wh1, g_Wh1);
    cudaGetSymbolAddress((void**)&Wh2, g_Wh2);
    cudaGetSymbolAddress((void**)&Hh,  g_Hh);
    cudaGetSymbolAddress((void**)&Y,   g_Y);

    cudaFuncSetAttribute((const void*)gemm_f16<false, true>,
                         cudaFuncAttributeMaxDynamicSharedMemorySize, GSMEM);
    cudaFuncSetAttribute((const void*)gemm_f16<true, false>,
                         cudaFuncAttributeMaxDynamicSharedMemorySize, GSMEM);

    dim3 blk(256);
    cast_x_kernel<<<NB, blk>>>(x, Xh);
    transpose_cast_kernel<<<dim3(NHID/256, NIN/32, NE), blk>>>(W1, Wh1, NIN, NHID);
    transpose_cast_kernel<<<dim3(NOUT/256, NHID/32, NE), blk>>>(W2, Wh2, NHID, NOUT);

    // GEMM1: pre-LN hidden written directly as fp16
    gemm_f16<false, true><<<dim3(NHID/128, NB/128, NE), blk, GSMEM>>>(
        Xh, Wh1, b1, Hh, NB, NHID, NIN);

    ln_gelu_f16<<<NE * NB, blk>>>(Hh, g1, be1);

    gemm_f16<true, false><<<dim3(NOUT/128, NB/128, NE), blk, GSMEM>>>(
        Hh, Wh2, b2, Y, NB, NOUT, NHID);

    combine_kernel<<<NB, blk>>>(wts, g2, be2, out);
}

// round 11
// speedup vs baseline: 8.1567x; 1.0348x over previous
#include <cuda_runtime.h>
#include <cuda_fp16.h>
#include <math.h>
#include <stdint.h>

#define NB   8192
#define NIN  1024
#define NHID 4096
#define NOUT 1024
#define NE   8
#define EPS  1e-5f

__device__ __align__(256) __half g_Xh [(size_t)NB * NIN];
__device__ __align__(256) __half g_Wh1[(size_t)NE * NHID * NIN];   // [E][N][K]
__device__ __align__(256) __half g_Wh2[(size_t)NE * NOUT * NHID];  // [E][N][K]
__device__ __align__(256) __half g_Hh [(size_t)NE * NB * NHID];    // pre-LN then act
__device__ __align__(256) __half g_Yh [(size_t)NE * NB * NOUT];

__device__ __forceinline__ float gelu_exact(float v) {
    return 0.5f * v * (1.0f + erff(v * 0.70710678118654752f));
}
__device__ __forceinline__ void block_sum2(float& s, float& s2) {
    __shared__ float sh[2][8];
    #pragma unroll
    for (int o = 16; o > 0; o >>= 1) {
        s  += __shfl_xor_sync(0xffffffffu, s,  o);
        s2 += __shfl_xor_sync(0xffffffffu, s2, o);
    }
    const int w = threadIdx.x >> 5, lane = threadIdx.x & 31;
    if (lane == 0) { sh[0][w] = s; sh[1][w] = s2; }
    __syncthreads();
    float t = 0.f, t2 = 0.f;
    const int nw = blockDim.x >> 5;
    for (int i = 0; i < nw; i++) { t += sh[0][i]; t2 += sh[1][i]; }
    s = t; s2 = t2;
    __syncthreads();
}
__device__ __forceinline__ uint32_t packh2(float a, float b) {
    __half2 h = __floats2half2_rn(a, b);
    return *reinterpret_cast<uint32_t*>(&h);
}

// ---------------- prep kernels ----------------
__global__ __launch_bounds__(256)
void cast_x_kernel(const float* __restrict__ X, __half* __restrict__ P)
{
    const size_t row = blockIdx.x;
    const int tid = threadIdx.x;
    const float4 v = ((const float4*)(X + row * NIN))[tid];
    *(uint2*)(P + row * NIN + tid * 4) = make_uint2(packh2(v.x, v.y), packh2(v.z, v.w));
}

__global__ __launch_bounds__(256)
void transpose_cast_kernel(const float* __restrict__ W, __half* __restrict__ Wh,
                           int K, int N)
{
    __shared__ float s[32][257];
    const int tid = threadIdx.x;
    const int e = blockIdx.z, n0 = blockIdx.x * 256, k0 = blockIdx.y * 32;
    const float* We = W + (size_t)e * K * N;
    for (int r = 0; r < 32; r++)
        s[r][tid] = We[(size_t)(k0 + r) * N + n0 + tid];
    __syncthreads();
    uint32_t buf[16];
    #pragma unroll
    for (int r = 0; r < 32; r += 2)
        buf[r >> 1] = packh2(s[r][tid], s[r + 1][tid]);
    __half* dst = Wh + ((size_t)e * N + n0 + tid) * (size_t)K + k0;
    #pragma unroll
    for (int j = 0; j < 4; j++)
        *(uint4*)(dst + j * 8) = ((const uint4*)buf)[j];
}

// ---------------- fp16 mma.sync GEMM ----------------
// C[e][M,N] = A([e]) @ B[e]^T + bias[e].  A,B fp16 K-major rows.
// CTA 128x128, 4 warps (2M x 2N), warp 64x64, BK=64, 3-stage cp.async,
// 2 CTAs/SM, fragment double-buffering, one barrier per k-block.
#define STG_A   16384
#define STG_B   16384
#define STG     (STG_A + STG_B)
#define GSMEM   (3 * STG)

template<bool A_EXP, bool OUT_F16>
__global__ void __launch_bounds__(128, 2)
gemm_f16(const __half* __restrict__ Ap, const __half* __restrict__ Bp,
         const float* __restrict__ bias, void* __restrict__ Cv,
         int M, int N, int K)
{
    extern __shared__ char smem[];
    const uint32_t sb = (uint32_t)__cvta_generic_to_shared(smem);
    const int tid = threadIdx.x;
    const int lane = tid & 31, wid = tid >> 5;
    const int wm = wid & 1, wn = wid >> 1;
    const int e = blockIdx.z;
    const int row0 = blockIdx.y * 128, col0 = blockIdx.x * 128;
    const size_t rowbytes = (size_t)K * 2;
    const char* Ab = (const char*)Ap + ((A_EXP ? (size_t)e * M : (size_t)0) + row0) * rowbytes;
    const char* Bb = (const char*)Bp + ((size_t)e * N + col0) * rowbytes;
    const int S = K >> 6;

    auto load_stage = [&](int s) {
        const int buf = s % 3;
        const uint32_t a0 = sb + (uint32_t)buf * STG, b0 = a0 + STG_A;
        #pragma unroll
        for (int k = 0; k < 8; k++) {
            const int c = tid + k * 128;
            const int row = c >> 3, cb = (c & 7) * 16;
            uint32_t off = (uint32_t)(row * 128 + cb);
            off ^= (off >> 3) & 0x70;
            asm volatile("cp.async.cg.shared.global [%0], [%1], 16;"
                         :: "r"(a0 + off),
                            "l"(Ab + (size_t)row * rowbytes + (size_t)s * 128 + cb));
        }
        #pragma unroll
        for (int k = 0; k < 8; k++) {
            const int c = tid + k * 128;
            const int row = c >> 3, cb = (c & 7) * 16;
            uint32_t off = (uint32_t)(row * 128 + cb);
            off ^= (off >> 3) & 0x70;
            asm volatile("cp.async.cg.shared.global [%0], [%1], 16;"
                         :: "r"(b0 + off),
                            "l"(Bb + (size_t)row * rowbytes + (size_t)s * 128 + cb));
        }
        asm volatile("cp.async.commit_group;" ::: "memory");
    };

    float acc[4][8][4] = {};

    load_stage(0);
    load_stage(1);

    const int arow = wm * 64 + (lane & 15);
    const int acolsel = (lane >> 4) << 4;
    const int brow_l = ((lane >> 4) << 3) + (lane & 7);
    const int bcolsel = ((lane >> 3) & 1) << 4;

    uint32_t afr[2][4][4], bfr[2][4][4];

    auto load_frags = [&](int slot, uint32_t asA, uint32_t asB, int h) {
        const int acol = h * 32 + acolsel;
        #pragma unroll
        for (int i = 0; i < 4; i++) {
            uint32_t byt = (uint32_t)((arow + i * 16) * 128 + acol);
            byt ^= (byt >> 3) & 0x70;
            asm volatile(
                "ldmatrix.sync.aligned.m8n8.x4.shared.b16 {%0,%1,%2,%3}, [%4];"
                : "=r"(afr[slot][i][0]), "=r"(afr[slot][i][1]),
                  "=r"(afr[slot][i][2]), "=r"(afr[slot][i][3])
                : "r"(asA + byt));
        }
        const int bcol = h * 32 + bcolsel;
        #pragma unroll
        for (int j2 = 0; j2 < 4; j2++) {
            const int brow = wn * 64 + j2 * 16 + brow_l;
            uint32_t byt = (uint32_t)(brow * 128 + bcol);
            byt ^= (byt >> 3) & 0x70;
            asm volatile(
                "ldmatrix.sync.aligned.m8n8.x4.shared.b16 {%0,%1,%2,%3}, [%4];"
                : "=r"(bfr[slot][j2][0]), "=r"(bfr[slot][j2][1]),
                  "=r"(bfr[slot][j2][2]), "=r"(bfr[slot][j2][3])
                : "r"(asB + byt));
        }
    };

    for (int kb = 0; kb < S; kb++) {
        asm volatile("cp.async.wait_group 1;" ::: "memory");
        __syncthreads();
        if (kb + 2 < S) load_stage(kb + 2);
        else asm volatile("cp.async.commit_group;" ::: "memory");

        const int buf = kb % 3;
        const uint32_t asA = sb + (uint32_t)buf * STG;
        const uint32_t asB = asA + STG_A;

        load_frags(0, asA, asB, 0);
        #pragma unroll
        for (int h = 0; h < 4; h++) {
            const int cur = h & 1, nxt = cur ^ 1;
            if (h < 3) load_frags(nxt, asA, asB, h + 1);
            #pragma unroll
            for (int i = 0; i < 4; i++)
                #pragma unroll
                for (int j2 = 0; j2 < 4; j2++)
                    #pragma unroll
                    for (int t = 0; t < 2; t++) {
                        float* d = acc[i][j2 * 2 + t];
                        asm volatile(
                            "mma.sync.aligned.m16n8k16.row.col.f32.f16.f16.f32 "
                            "{%0,%1,%2,%3},{%4,%5,%6,%7},{%8,%9},{%0,%1,%2,%3};"
                            : "+f"(d[0]), "+f"(d[1]), "+f"(d[2]), "+f"(d[3])
                            : "r"(afr[cur][i][0]), "r"(afr[cur][i][1]),
                              "r"(afr[cur][i][2]), "r"(afr[cur][i][3]),
                              "r"(bfr[cur][j2][2 * t]), "r"(bfr[cur][j2][2 * t + 1]));
                    }
        }
    }

    // Epilogue: warp owns 64x64 at (row0 + wm*64, col0 + wn*64)
    const float* bz = bias + (size_t)e * N + col0 + wn * 64;
    const int r = lane >> 2, cc = (lane & 3) * 2;
    if (OUT_F16) {
        __half* Cb = (__half*)Cv + (size_t)e * M * N
                   + (size_t)(row0 + wm * 64) * N + col0 + wn * 64;
        #pragma unroll
        for (int i = 0; i < 4; i++)
            #pragma unroll
            for (int j = 0; j < 8; j++) {
                const int col = j * 8 + cc;
                const float b0v = bz[col], b1v = bz[col + 1];
                *(uint32_t*)(Cb + (size_t)(i * 16 + r) * N + col) =
                    packh2(acc[i][j][0] + b0v, acc[i][j][1] + b1v);
                *(uint32_t*)(Cb + (size_t)(i * 16 + r + 8) * N + col) =
                    packh2(acc[i][j][2] + b0v, acc[i][j][3] + b1v);
            }
    } else {
        float* Cb = (float*)Cv + (size_t)e * M * N
                  + (size_t)(row0 + wm * 64) * N + col0 + wn * 64;
        #pragma unroll
        for (int i = 0; i < 4; i++)
            #pragma unroll
            for (int j = 0; j < 8; j++) {
                const int col = j * 8 + cc;
                const float b0v = bz[col], b1v = bz[col + 1];
                *(float2*)(Cb + (size_t)(i * 16 + r) * N + col) =
                    make_float2(acc[i][j][0] + b0v, acc[i][j][1] + b1v);
                *(float2*)(Cb + (size_t)(i * 16 + r + 8) * N + col) =
                    make_float2(acc[i][j][2] + b0v, acc[i][j][3] + b1v);
            }
    }
}

// ---------------- in-place LN + GELU on fp16 rows ----------------
__global__ __launch_bounds__(256)
void ln_gelu_f16(__half* __restrict__ Hh,
                 const float* __restrict__ gamma, const float* __restrict__ beta)
{
    const size_t row = blockIdx.x;
    const int e = (int)(row / NB);
    const int tid = threadIdx.x;
    uint4* xr = (uint4*)(Hh + row * (size_t)NHID);
    const float4* gp = (const float4*)(gamma + (size_t)e * NHID);
    const float4* bp = (const float4*)(beta  + (size_t)e * NHID);

    uint4 u[2];
    float v[16];
    float s = 0.f, s2 = 0.f;
    #pragma unroll
    for (int i = 0; i < 2; i++) {
        u[i] = xr[i * 256 + tid];
        const uint32_t* w32 = (const uint32_t*)&u[i];
        #pragma unroll
        for (int q = 0; q < 4; q++) {
            float2 f = __half22float2(*(const __half2*)&w32[q]);
            v[i * 8 + q * 2]     = f.x;
            v[i * 8 + q * 2 + 1] = f.y;
            s  += f.x + f.y;
            s2 += f.x * f.x + f.y * f.y;
        }
    }
    block_sum2(s, s2);
    const float mean = s * (1.0f / NHID);
    const float rstd = rsqrtf(s2 * (1.0f / NHID) - mean * mean + EPS);

    #pragma unroll
    for (int i = 0; i < 2; i++) {
        uint4 o;
        uint32_t* ow = (uint32_t*)&o;
        #pragma unroll
        for (int q = 0; q < 2; q++) {
            const int eb = (i * 256 + tid) * 8 + q * 4;
            const float4 g4 = gp[eb >> 2], b4 = bp[eb >> 2];
            const float* vv = &v[i * 8 + q * 4];
            float a0 = gelu_exact((vv[0] - mean) * rstd * g4.x + b4.x);
            float a1 = gelu_exact((vv[1] - mean) * rstd * g4.y + b4.y);
            float a2 = gelu_exact((vv[2] - mean) * rstd * g4.z + b4.z);
            float a3 = gelu_exact((vv[3] - mean) * rstd * g4.w + b4.w);
            ow[q * 2]     = packh2(a0, a1);
            ow[q * 2 + 1] = packh2(a2, a3);
        }
        xr[i * 256 + tid] = o;
    }
}

// ---------------- final LN+GELU+weighted combine (fp16 Y) ----------------
__global__ __launch_bounds__(256)
void combine_kernel(const float* __restrict__ w,
                    const float* __restrict__ g2, const float* __restrict__ be2,
                    float* __restrict__ out)
{
    const int b = blockIdx.x, tid = threadIdx.x;
    float acc[4] = {0.f, 0.f, 0.f, 0.f};
    for (int e = 0; e < NE; e++) {
        const __half* yr = g_Yh + ((size_t)e * NB + b) * NOUT;
        const uint2 u = *(const uint2*)(yr + tid * 4);
        float2 f0 = __half22float2(*(const __half2*)&u.x);
        float2 f1 = __half22float2(*(const __half2*)&u.y);
        float vv[4] = {f0.x, f0.y, f1.x, f1.y};
        float s = vv[0] + vv[1] + vv[2] + vv[3];
        float s2 = vv[0]*vv[0] + vv[1]*vv[1] + vv[2]*vv[2] + vv[3]*vv[3];
        block_sum2(s, s2);
        const float mean = s * (1.0f / NOUT);
        const float rstd = rsqrtf(s2 * (1.0f / NOUT) - mean * mean + EPS);
        const float we = w[(size_t)b * NE + e];
        #pragma unroll
        for (int i = 0; i < 4; i++) {
            const int o = tid * 4 + i;
            const float val = (vv[i] - mean) * rstd * g2[(size_t)e * NOUT + o]
                              + be2[(size_t)e * NOUT + o];
            acc[i] += we * gelu_exact(val);
        }
    }
    float4 o4 = make_float4(acc[0], acc[1], acc[2], acc[3]);
    *(float4*)(out + (size_t)b * NOUT + tid * 4) = o4;
}

// ---------------------------------------------------------------------------
extern "C" void kernel_launch(void* const* d_in, const int* in_sizes, int n_in,
                              void* d_out, int out_size)
{
    const float* x   = (const float*)d_in[0];
    const float* wts = (const float*)d_in[1];
    const float* W1  = (const float*)d_in[2];
    const float* b1  = (const float*)d_in[3];
    const float* g1  = (const float*)d_in[4];
    const float* be1 = (const float*)d_in[5];
    const float* W2  = (const float*)d_in[6];
    const float* b2  = (const float*)d_in[7];
    const float* g2  = (const float*)d_in[8];
    const float* be2 = (const float*)d_in[9];
    float* out = (float*)d_out;

    __half *Xh, *Wh1, *Wh2, *Hh, *Yh;
    cudaGetSymbolAddress((void**)&Xh,  g_Xh);
    cudaGetSymbolAddress((void**)&Wh1, g_Wh1);
    cudaGetSymbolAddress((void**)&Wh2, g_Wh2);
    cudaGetSymbolAddress((void**)&Hh,  g_Hh);
    cudaGetSymbolAddress((void**)&Yh,  g_Yh);

    cudaFuncSetAttribute((const void*)gemm_f16<false, true>,
                         cudaFuncAttributeMaxDynamicSharedMemorySize, GSMEM);
    cudaFuncSetAttribute((const void*)gemm_f16<true, true>,
                         cudaFuncAttributeMaxDynamicSharedMemorySize, GSMEM);

    cast_x_kernel<<<NB, 256>>>(x, Xh);
    transpose_cast_kernel<<<dim3(NHID/256, NIN/32, NE), 256>>>(W1, Wh1, NIN, NHID);
    transpose_cast_kernel<<<dim3(NOUT/256, NHID/32, NE), 256>>>(W2, Wh2, NHID, NOUT);

    gemm_f16<false, true><<<dim3(NHID/128, NB/128, NE), 128, GSMEM>>>(
        Xh, Wh1, b1, Hh, NB, NHID, NIN);

    ln_gelu_f16<<<NE * NB, 256>>>(Hh, g1, be1);

    gemm_f16<true, true><<<dim3(NOUT/128, NB/128, NE), 128, GSMEM>>>(
        Hh, Wh2, b2, Yh, NB, NOUT, NHID);

    combine_kernel<<<NB, 256>>>(wts, g2, be2, out);
}